// round 11
// baseline (speedup 1.0000x reference)
#include <cuda_runtime.h>
#include <stdint.h>

// ---------------- problem constants ----------------
#define USER_N 100000
#define ITEM_N 50000
#define TAG_N  20000
#define NADJ   (USER_N + ITEM_N)   // 150000
#define MTAG   (ITEM_N + TAG_N)    // 70000
#define EADJ   2000000
#define ETAG   1000000
#define ESOC   1000000
#define ETOT   4000000
#define R4     16                    // D=64 floats = 16 float4
#define NELEM  (NADJ * R4)           // 2,400,000 float4
#define UELEM  (USER_N * R4)
#define IELEM  (ITEM_N * R4)
#define GELEM  (MTAG * R4)
#define TB     256

// sorted layout: adj [0, 2M), tag [2M, 3,000,064), soc [3,000,064, 4,000,128)
#define SOC_PAD   64
#define SORT_N    4000128
// bins: adj rows [0,150K) | tag rows [150K,220K) | soc rows [220K,320K)
#define NBINS  (NADJ + MTAG + USER_N)        // 320000
#define SOC_BIN0 (NADJ + MTAG)               // 220000
#define SCANB  313
#define NBINP  (SCANB * 1024)                // 320512 (padded)
#define EB     (ETOT / TB)                   // 15625
#define SPMMB  (NBINS / 8)                   // 40000 blocks (8 warps = 8 rows)
#define COMBB  ((NELEM + 2 * TB - 1) / (2 * TB))   // 4688

// ---------------- device scratch ----------------
__device__ float4 g_lat[NELEM];
__device__ float4 g_taglat[GELEM];
__device__ float4 g_tem[NELEM];           // fully rewritten by spmm each launch
__device__ float4 g_tg[GELEM];            // fully rewritten by spmm each launch
__device__ float4 g_soc[UELEM];           // fully rewritten by spmm each launch
__device__ uint4  g_bins4[NBINP / 4];     // histogram (zeroed by scatter each call)
__device__ uint4  g_binScan4[NBINP / 4];  // scatter cursors (rewritten each call)
__device__ uint4  g_rowStart4[NBINP / 4]; // pristine CSR row starts (rewritten)
__device__ uint32_t g_blkSum[SCANB];
__device__ uint32_t g_blkOff[SCANB];
__device__ uint4  g_sorted[SORT_N];       // (col, val_bits, local_idx, 0); pads stay 0

// ---------------- threefry-2x32-20 (JAX partitionable, bit-exact) ----------------
__device__ __forceinline__ uint32_t d_rotl(uint32_t v, int r) {
    return __funnelshift_l(v, v, r);
}
__device__ __forceinline__ uint32_t tf_bits(uint32_t K1, uint32_t K2, uint32_t ctr) {
    uint32_t ks2 = K1 ^ K2 ^ 0x1BD11BDAu;
    uint32_t x0 = K1;
    uint32_t x1 = ctr + K2;
#define TF_R4(a,b,c,d)                                        \
    x0 += x1; x1 = d_rotl(x1,a); x1 ^= x0;                    \
    x0 += x1; x1 = d_rotl(x1,b); x1 ^= x0;                    \
    x0 += x1; x1 = d_rotl(x1,c); x1 ^= x0;                    \
    x0 += x1; x1 = d_rotl(x1,d); x1 ^= x0;
    TF_R4(13,15,26,6)   x0 += K2;  x1 += ks2 + 1u;
    TF_R4(17,29,16,24)  x0 += ks2; x1 += K1  + 2u;
    TF_R4(13,15,26,6)   x0 += K1;  x1 += K2  + 3u;
    TF_R4(17,29,16,24)  x0 += K2;  x1 += ks2 + 4u;
    TF_R4(13,15,26,6)   x0 += ks2; x1 += K1  + 5u;
#undef TF_R4
    return x0 ^ x1;
}

static inline uint32_t h_rotl(uint32_t v, int r) { return (v << r) | (v >> (32 - r)); }
static void h_threefry(uint32_t K1, uint32_t K2, uint32_t x0, uint32_t x1,
                       uint32_t* o0, uint32_t* o1) {
    uint32_t ks[3] = {K1, K2, K1 ^ K2 ^ 0x1BD11BDAu};
    static const int rots[2][4] = {{13,15,26,6},{17,29,16,24}};
    x0 += ks[0]; x1 += ks[1];
    for (int g = 0; g < 5; ++g) {
        const int* rr = rots[g & 1];
        for (int j = 0; j < 4; ++j) { x0 += x1; x1 = h_rotl(x1, rr[j]); x1 ^= x0; }
        x0 += ks[(g + 1) % 3];
        x1 += ks[(g + 2) % 3] + (uint32_t)(g + 1);
    }
    *o0 = x0; *o1 = x1;
}

// ---------------- helpers ----------------
__device__ __forceinline__ float4 leaky4(float4 h) {
    h.x = h.x >= 0.f ? h.x : 0.5f * h.x;
    h.y = h.y >= 0.f ? h.y : 0.5f * h.y;
    h.z = h.z >= 0.f ? h.z : 0.5f * h.z;
    h.w = h.w >= 0.f ? h.w : 0.5f * h.w;
    return h;
}
__device__ __forceinline__ float4 add4(float4 a, float4 b) {
    return make_float4(a.x + b.x, a.y + b.y, a.z + b.z, a.w + b.w);
}

// ---------------- sort pipeline ----------------
__global__ void hist_kernel(const int* __restrict__ ar,
                            const int* __restrict__ tr,
                            const int* __restrict__ sr) {
    unsigned tid = blockIdx.x * TB + threadIdx.x;      // < ETOT
    unsigned bin;
    if (tid < EADJ)               bin = (unsigned)__ldg(ar + tid);
    else if (tid < EADJ + ETAG)   bin = NADJ + (unsigned)__ldg(tr + (tid - EADJ));
    else                          bin = SOC_BIN0 + (unsigned)__ldg(sr + (tid - EADJ - ETAG));
    atomicAdd(&((uint32_t*)g_bins4)[bin], 1u);
}

__global__ void scanA_kernel() {
    unsigned t = threadIdx.x, b = blockIdx.x;
    uint4 v = g_bins4[b * 256 + t];
    uint32_t sum = v.x + v.y + v.z + v.w;
    uint32_t incl = sum;
#pragma unroll
    for (int d = 1; d < 32; d <<= 1) {
        uint32_t n = __shfl_up_sync(0xffffffffu, incl, d);
        if ((t & 31u) >= (unsigned)d) incl += n;
    }
    __shared__ uint32_t ws[8], wo[8];
    if ((t & 31u) == 31u) ws[t >> 5] = incl;
    __syncthreads();
    if (t == 0) {
        uint32_t run = 0;
#pragma unroll
        for (int i = 0; i < 8; ++i) { wo[i] = run; run += ws[i]; }
        g_blkSum[b] = run;
    }
    __syncthreads();
    uint32_t excl = incl - sum + wo[t >> 5];
    uint4 o;
    o.x = excl; o.y = excl + v.x; o.z = o.y + v.y; o.w = o.z + v.z;
    g_binScan4[b * 256 + t] = o;
}

__global__ void scanB_kernel() {
    unsigned t = threadIdx.x;                 // 512 threads
    uint32_t sum = (t < SCANB) ? g_blkSum[t] : 0u;
    uint32_t incl = sum;
#pragma unroll
    for (int d = 1; d < 32; d <<= 1) {
        uint32_t n = __shfl_up_sync(0xffffffffu, incl, d);
        if ((t & 31u) >= (unsigned)d) incl += n;
    }
    __shared__ uint32_t ws[16], wo[16];
    if ((t & 31u) == 31u) ws[t >> 5] = incl;
    __syncthreads();
    if (t == 0) {
        uint32_t run = 0;
#pragma unroll
        for (int i = 0; i < 16; ++i) { wo[i] = run; run += ws[i]; }
    }
    __syncthreads();
    if (t < SCANB) g_blkOff[t] = incl - sum + wo[t >> 5];
}

// finalize bin starts (+64 soc-region pad shift); mirror into pristine rowStart.
// Padded bins (>= NBINS) scan to SORT_N -> rowStart[NBINS] sentinel comes free.
__global__ void scanC_kernel() {
    unsigned t = threadIdx.x, b = blockIdx.x;
    unsigned idx4 = b * 256 + t;
    uint32_t add = g_blkOff[b] + ((idx4 >= SOC_BIN0 / 4) ? SOC_PAD : 0u);
    uint4 v = g_binScan4[idx4];
    v.x += add; v.y += add; v.z += add; v.w += add;
    g_binScan4[idx4]  = v;     // mutable scatter cursors
    g_rowStart4[idx4] = v;     // pristine CSR row starts for spmm
}

// scatter edges into row-sorted order; re-zero histogram bins
__global__ void scatter_kernel(const int* __restrict__ ar, const int* __restrict__ ac,
                               const float* __restrict__ av,
                               const int* __restrict__ tr, const int* __restrict__ tc,
                               const float* __restrict__ tv,
                               const int* __restrict__ sr, const int* __restrict__ sc,
                               const float* __restrict__ sv) {
    unsigned tid = blockIdx.x * TB + threadIdx.x;      // < ETOT
    unsigned e, bin; int c; float v;
    if (tid < EADJ) {
        e = tid;               bin = (unsigned)__ldg(ar + e);            c = __ldg(ac + e); v = __ldg(av + e);
    } else if (tid < EADJ + ETAG) {
        e = tid - EADJ;        bin = NADJ + (unsigned)__ldg(tr + e);     c = __ldg(tc + e); v = __ldg(tv + e);
    } else {
        e = tid - EADJ - ETAG; bin = SOC_BIN0 + (unsigned)__ldg(sr + e); c = __ldg(sc + e); v = __ldg(sv + e);
    }
    unsigned pos = atomicAdd(&((uint32_t*)g_binScan4)[bin], 1u);
    g_sorted[pos] = make_uint4((unsigned)c, __float_as_uint(v), e, 0u);
    if (tid < NBINP) ((uint32_t*)g_bins4)[tid] = 0u;   // zero-on-exit for hist
}

// ---------------- warp-per-row CSR SPMM (no atomics, no zeroing needed) --------
// Warp = one output row (bin). lane = float2 chunk of D=64. Loads <=32 records
// per pass (1/lane, coalesced), one threefry per edge total, 8-wide MLP gather
// batches, register accumulation, single coalesced STG. Pad records have val=0.
template <int LAYER>
__global__ void spmm_kernel(const float4* __restrict__ u4,
                            const float4* __restrict__ i4,
                            const float4* __restrict__ t4,
                            uint32_t ka1, uint32_t ka2, uint32_t kt1, uint32_t kt2,
                            uint32_t ku1, uint32_t ku2) {
    unsigned lane = threadIdx.x & 31u;
    unsigned bin  = blockIdx.x * 8u + (threadIdx.x >> 5);    // < NBINS
    float2* outp; int mode; uint32_t k1, k2;
    if (bin < NADJ)          { mode = 0; outp = (float2*)g_tem + bin * 32u;              k1 = ka1; k2 = ka2; }
    else if (bin < SOC_BIN0) { mode = 1; outp = (float2*)g_tg  + (bin - NADJ) * 32u;     k1 = kt1; k2 = kt2; }
    else                     { mode = 2; outp = (float2*)g_soc + (bin - SOC_BIN0) * 32u; k1 = ku1; k2 = ku2; }
    const uint32_t* rs = (const uint32_t*)g_rowStart4;
    unsigned start = __ldg(rs + bin);
    unsigned end   = __ldg(rs + bin + 1);    // pads between regions have val=0

    float2 acc = make_float2(0.f, 0.f);
    for (unsigned base = start; base < end; base += 32u) {
        unsigned n = min(32u, end - base);
        uint4 rec = make_uint4(0u, 0u, 0u, 0u);
        if (lane < n) rec = __ldg(&g_sorted[base + lane]);
        // one threefry per edge (rec.z = original per-graph index); val=0 pads drop out
        uint32_t bits = tf_bits(k1, k2, rec.z);
        float u    = __uint_as_float((bits >> 9) | 0x3f800000u) - 1.0f;
        float mval = (__uint_as_float(rec.y) * floorf(u + 0.9f)) * (float)(1.0 / 0.9);

        for (unsigned j0 = 0; j0 < n; j0 += 8u) {
            float mv[8]; int cc[8]; float2 xv[8];
#pragma unroll
            for (int j = 0; j < 8; ++j) {
                mv[j] = __shfl_sync(0xffffffffu, mval,       (int)(j0 + j));
                cc[j] = __shfl_sync(0xffffffffu, (int)rec.x, (int)(j0 + j));
            }
#pragma unroll
            for (int j = 0; j < 8; ++j) {
                if (mv[j] != 0.f) {
                    int c = cc[j];
                    const float2* x;
                    if (LAYER == 0) {
                        if (mode == 1)
                            x = (c < ITEM_N) ? ((const float2*)i4 + (unsigned)c * 32u)
                                             : ((const float2*)t4 + (unsigned)(c - ITEM_N) * 32u);
                        else
                            x = (c < USER_N) ? ((const float2*)u4 + (unsigned)c * 32u)
                                             : ((const float2*)i4 + (unsigned)(c - USER_N) * 32u);
                    } else {
                        if (mode == 1)
                            x = (c < ITEM_N) ? ((const float2*)g_lat + (unsigned)(USER_N + c) * 32u)
                                             : ((const float2*)g_taglat + (unsigned)c * 32u);
                        else
                            x = (const float2*)g_lat + (unsigned)c * 32u;
                    }
                    xv[j] = __ldg(x + lane);
                }
            }
#pragma unroll
            for (int j = 0; j < 8; ++j) {
                if (mv[j] != 0.f) {
                    acc.x += mv[j] * xv[j].x;
                    acc.y += mv[j] * xv[j].y;
                }
            }
        }
    }
    outp[lane] = acc;     // full coverage: every row fully rewritten, no zeroing
}

// combine-mid: lat = leaky(tem)+leaky(soc|tg); taglat(tag part) = leaky(tg).
// No zeroing anywhere. All loads before all stores.
__global__ void mid_kernel() {
    const float4 z = make_float4(0.f, 0.f, 0.f, 0.f);
    unsigned base = blockIdx.x * (2u * TB) + threadIdx.x;
    unsigned ia = base, ib = base + TB;
    bool va = ia < NELEM, vb = ib < NELEM;
    unsigned a = va ? ia : 0u, b = vb ? ib : 0u;
    bool ua = a < UELEM, ub = b < UELEM;
    bool ga = (a >= IELEM) & (a < GELEM);
    bool gb = (b >= IELEM) & (b < GELEM);
    float4 ta  = g_tem[a];
    float4 tb4 = g_tem[b];
    float4 sa  = ua ? g_soc[a] : g_tg[a - UELEM];
    float4 sb  = ub ? g_soc[b] : g_tg[b - UELEM];
    float4 g0a = ga ? g_tg[a] : z;
    float4 g0b = gb ? g_tg[b] : z;
    float4 oa = add4(leaky4(ta),  leaky4(sa));
    float4 ob = add4(leaky4(tb4), leaky4(sb));
    if (va) {
        g_lat[a] = oa;
        if (ga) g_taglat[a] = leaky4(g0a);
    }
    if (vb) {
        g_lat[b] = ob;
        if (gb) g_taglat[b] = leaky4(g0b);
    }
}

// combine-final: out = (u|i) + g_lat + leaky(tem) + leaky(soc|tg). No zeroing.
__global__ void fin_kernel(float4* __restrict__ out,
                           const float4* __restrict__ u4,
                           const float4* __restrict__ i4) {
    unsigned base = blockIdx.x * (2u * TB) + threadIdx.x;
    unsigned ia = base, ib = base + TB;
    bool va = ia < NELEM, vb = ib < NELEM;
    unsigned a = va ? ia : 0u, b = vb ? ib : 0u;
    bool ua = a < UELEM, ub = b < UELEM;
    float4 ta  = g_tem[a];
    float4 tb4 = g_tem[b];
    float4 sa  = ua ? g_soc[a] : g_tg[a - UELEM];
    float4 sb  = ub ? g_soc[b] : g_tg[b - UELEM];
    float4 la  = g_lat[a];
    float4 lb  = g_lat[b];
    float4 ea  = ua ? __ldg(u4 + a) : __ldg(i4 + a - UELEM);
    float4 eb  = ub ? __ldg(u4 + b) : __ldg(i4 + b - UELEM);
    float4 l2a = add4(leaky4(ta),  leaky4(sa));
    float4 l2b = add4(leaky4(tb4), leaky4(sb));
    if (va) out[a] = add4(add4(ea, la), l2a);
    if (vb) out[b] = add4(add4(eb, lb), l2b);
}

// ---------------- launch ----------------
extern "C" void kernel_launch(void* const* d_in, const int* in_sizes, int n_in,
                              void* d_out, int out_size) {
    const float4* uE = (const float4*)d_in[0];
    const float4* iE = (const float4*)d_in[1];
    const float4* tE = (const float4*)d_in[2];
    const int*   ar = (const int*)d_in[3];
    const int*   ac = (const int*)d_in[4];
    const float* av = (const float*)d_in[5];
    const int*   tr = (const int*)d_in[6];
    const int*   tc = (const int*)d_in[7];
    const float* tv = (const float*)d_in[8];
    const int*   sr = (const int*)d_in[9];
    const int*   sc = (const int*)d_in[10];
    const float* sv = (const float*)d_in[11];
    float4* out = (float4*)d_out;

    // jax.random.key(42) -> (0, 42); fold_in(key, j) = threefry2x32(key, (0, j))
    uint32_t fk[6][2];
    for (uint32_t j = 0; j < 6; ++j)
        h_threefry(0u, 42u, 0u, j, &fk[j][0], &fk[j][1]);

    // row-sort the edge lists (shared by both layers); builds CSR row starts
    hist_kernel<<<EB, TB>>>(ar, tr, sr);
    scanA_kernel<<<SCANB, 256>>>();
    scanB_kernel<<<1, 512>>>();
    scanC_kernel<<<SCANB, 256>>>();
    scatter_kernel<<<EB, TB>>>(ar, ac, av, tr, tc, tv, sr, sc, sv);

    // layer 0: warp-per-row CSR spmm from input embeddings
    spmm_kernel<0><<<SPMMB, TB>>>(uE, iE, tE,
                                  fk[0][0], fk[0][1], fk[1][0], fk[1][1],
                                  fk[2][0], fk[2][1]);
    mid_kernel<<<COMBB, TB>>>();
    // layer 1: warp-per-row CSR spmm from g_lat / g_taglat
    spmm_kernel<1><<<SPMMB, TB>>>(uE, iE, tE,
                                  fk[3][0], fk[3][1], fk[4][0], fk[4][1],
                                  fk[5][0], fk[5][1]);
    fin_kernel<<<COMBB, TB>>>(out, uE, iE);
}

// round 13
// speedup vs baseline: 1.4844x; 1.4844x over previous
#include <cuda_runtime.h>
#include <stdint.h>

// ---------------- problem constants ----------------
#define USER_N 100000
#define ITEM_N 50000
#define TAG_N  20000
#define NADJ   (USER_N + ITEM_N)   // 150000
#define MTAG   (ITEM_N + TAG_N)    // 70000
#define EADJ   2000000
#define ETAG   1000000
#define ESOC   1000000
#define ETOT   4000000
#define R4     16                    // D=64 floats = 16 float4
#define NELEM  (NADJ * R4)           // 2,400,000 float4
#define UELEM  (USER_N * R4)
#define IELEM  (ITEM_N * R4)
#define GELEM  (MTAG * R4)
#define TELEM  (TAG_N * R4)
#define TB     256

// sorted layout, regions padded to 256-edge multiples:
// adj [0, 2,000,128) | tag [2,000,128, 3,000,320) | soc [3,000,320, 4,000,512)
#define TAG_BASE  2000128
#define SOC_BASE  3000320
#define SORT_N    4000512
#define EPB    256                   // edges per spmm block (32 per warp)
#define A_BLK  (TAG_BASE / EPB)              // 7813
#define T_BLK  ((SOC_BASE - TAG_BASE) / EPB) // 3907
#define S_BLK  ((SORT_N - SOC_BASE) / EPB)   // 3907
#define SPMMB  (A_BLK + T_BLK + S_BLK)       // 15627
#define COMBB  ((NELEM + 2 * TB - 1) / (2 * TB))   // 4688

// bins: adj rows [0,150K) | tag rows [150K,220K) | soc rows [220K,320K)
#define NBINS  (NADJ + MTAG + USER_N)        // 320000
#define SOC_BIN0 (NADJ + MTAG)               // 220000
#define SCANB  313
#define NBINP  (SCANB * 1024)                // 320512 (padded)
#define EB     (ETOT / TB)                   // 15625

// ---------------- device scratch (zero-init at load; zero-on-exit invariant) ----
__device__ float4 g_lat[NELEM];
__device__ float4 g_taglat[GELEM];
__device__ float4 g_tem[NELEM];
__device__ float4 g_tg[2][GELEM];         // double-buffered (no zero-race)
__device__ float4 g_soc[UELEM];
__device__ uint4  g_bins4[NBINP / 4];     // histogram (zeroed by scatter each call)
__device__ uint4  g_binScan4[NBINP / 4];  // scatter cursors (rewritten each call)
__device__ uint32_t g_blkSum[SCANB];
__device__ uint32_t g_blkOff[SCANB];
__device__ uint4  g_sorted[SORT_N];       // (row, col, val_bits, local_idx); pads stay 0

// ---------------- threefry-2x32-20 (JAX partitionable, bit-exact) ----------------
__device__ __forceinline__ uint32_t d_rotl(uint32_t v, int r) {
    return __funnelshift_l(v, v, r);
}
__device__ __forceinline__ uint32_t tf_bits(uint32_t K1, uint32_t K2, uint32_t ctr) {
    uint32_t ks2 = K1 ^ K2 ^ 0x1BD11BDAu;
    uint32_t x0 = K1;
    uint32_t x1 = ctr + K2;
#define TF_R4(a,b,c,d)                                        \
    x0 += x1; x1 = d_rotl(x1,a); x1 ^= x0;                    \
    x0 += x1; x1 = d_rotl(x1,b); x1 ^= x0;                    \
    x0 += x1; x1 = d_rotl(x1,c); x1 ^= x0;                    \
    x0 += x1; x1 = d_rotl(x1,d); x1 ^= x0;
    TF_R4(13,15,26,6)   x0 += K2;  x1 += ks2 + 1u;
    TF_R4(17,29,16,24)  x0 += ks2; x1 += K1  + 2u;
    TF_R4(13,15,26,6)   x0 += K1;  x1 += K2  + 3u;
    TF_R4(17,29,16,24)  x0 += K2;  x1 += ks2 + 4u;
    TF_R4(13,15,26,6)   x0 += ks2; x1 += K1  + 5u;
#undef TF_R4
    return x0 ^ x1;
}

static inline uint32_t h_rotl(uint32_t v, int r) { return (v << r) | (v >> (32 - r)); }
static void h_threefry(uint32_t K1, uint32_t K2, uint32_t x0, uint32_t x1,
                       uint32_t* o0, uint32_t* o1) {
    uint32_t ks[3] = {K1, K2, K1 ^ K2 ^ 0x1BD11BDAu};
    static const int rots[2][4] = {{13,15,26,6},{17,29,16,24}};
    x0 += ks[0]; x1 += ks[1];
    for (int g = 0; g < 5; ++g) {
        const int* rr = rots[g & 1];
        for (int j = 0; j < 4; ++j) { x0 += x1; x1 = h_rotl(x1, rr[j]); x1 ^= x0; }
        x0 += ks[(g + 1) % 3];
        x1 += ks[(g + 2) % 3] + (uint32_t)(g + 1);
    }
    *o0 = x0; *o1 = x1;
}

// ---------------- helpers ----------------
__device__ __forceinline__ float4 leaky4(float4 h) {
    h.x = h.x >= 0.f ? h.x : 0.5f * h.x;
    h.y = h.y >= 0.f ? h.y : 0.5f * h.y;
    h.z = h.z >= 0.f ? h.z : 0.5f * h.z;
    h.w = h.w >= 0.f ? h.w : 0.5f * h.w;
    return h;
}
__device__ __forceinline__ float4 add4(float4 a, float4 b) {
    return make_float4(a.x + b.x, a.y + b.y, a.z + b.z, a.w + b.w);
}

// ---------------- sort pipeline ----------------
__global__ void hist_kernel(const int* __restrict__ ar,
                            const int* __restrict__ tr,
                            const int* __restrict__ sr) {
    unsigned tid = blockIdx.x * TB + threadIdx.x;      // < ETOT
    unsigned bin;
    if (tid < EADJ)               bin = (unsigned)__ldg(ar + tid);
    else if (tid < EADJ + ETAG)   bin = NADJ + (unsigned)__ldg(tr + (tid - EADJ));
    else                          bin = SOC_BIN0 + (unsigned)__ldg(sr + (tid - EADJ - ETAG));
    atomicAdd(&((uint32_t*)g_bins4)[bin], 1u);
}

__global__ void scanA_kernel() {
    unsigned t = threadIdx.x, b = blockIdx.x;
    uint4 v = g_bins4[b * 256 + t];
    uint32_t sum = v.x + v.y + v.z + v.w;
    uint32_t incl = sum;
#pragma unroll
    for (int d = 1; d < 32; d <<= 1) {
        uint32_t n = __shfl_up_sync(0xffffffffu, incl, d);
        if ((t & 31u) >= (unsigned)d) incl += n;
    }
    __shared__ uint32_t ws[8], wo[8];
    if ((t & 31u) == 31u) ws[t >> 5] = incl;
    __syncthreads();
    if (t == 0) {
        uint32_t run = 0;
#pragma unroll
        for (int i = 0; i < 8; ++i) { wo[i] = run; run += ws[i]; }
        g_blkSum[b] = run;
    }
    __syncthreads();
    uint32_t excl = incl - sum + wo[t >> 5];
    uint4 o;
    o.x = excl; o.y = excl + v.x; o.z = o.y + v.y; o.w = o.z + v.z;
    g_binScan4[b * 256 + t] = o;
}

__global__ void scanB_kernel() {
    unsigned t = threadIdx.x;                 // 512 threads
    uint32_t sum = (t < SCANB) ? g_blkSum[t] : 0u;
    uint32_t incl = sum;
#pragma unroll
    for (int d = 1; d < 32; d <<= 1) {
        uint32_t n = __shfl_up_sync(0xffffffffu, incl, d);
        if ((t & 31u) >= (unsigned)d) incl += n;
    }
    __shared__ uint32_t ws[16], wo[16];
    if ((t & 31u) == 31u) ws[t >> 5] = incl;
    __syncthreads();
    if (t == 0) {
        uint32_t run = 0;
#pragma unroll
        for (int i = 0; i < 16; ++i) { wo[i] = run; run += ws[i]; }
    }
    __syncthreads();
    if (t < SCANB) g_blkOff[t] = incl - sum + wo[t >> 5];
}

// finalize bin starts; region pad shifts: tag bins +128, soc bins +320
__global__ void scanC_kernel() {
    unsigned t = threadIdx.x, b = blockIdx.x;
    unsigned idx4 = b * 256 + t;
    uint32_t add = g_blkOff[b]
                 + ((idx4 >= NADJ / 4)     ? 128u : 0u)
                 + ((idx4 >= SOC_BIN0 / 4) ? 192u : 0u);
    uint4 v = g_binScan4[idx4];
    v.x += add; v.y += add; v.z += add; v.w += add;
    g_binScan4[idx4] = v;
}

// scatter edges into row-sorted order; re-zero histogram bins
__global__ void scatter_kernel(const int* __restrict__ ar, const int* __restrict__ ac,
                               const float* __restrict__ av,
                               const int* __restrict__ tr, const int* __restrict__ tc,
                               const float* __restrict__ tv,
                               const int* __restrict__ sr, const int* __restrict__ sc,
                               const float* __restrict__ sv) {
    unsigned tid = blockIdx.x * TB + threadIdx.x;      // < ETOT
    unsigned e, bin; int r, c; float v;
    if (tid < EADJ) {
        e = tid;               r = __ldg(ar + e); c = __ldg(ac + e); v = __ldg(av + e); bin = (unsigned)r;
    } else if (tid < EADJ + ETAG) {
        e = tid - EADJ;        r = __ldg(tr + e); c = __ldg(tc + e); v = __ldg(tv + e); bin = NADJ + (unsigned)r;
    } else {
        e = tid - EADJ - ETAG; r = __ldg(sr + e); c = __ldg(sc + e); v = __ldg(sv + e); bin = SOC_BIN0 + (unsigned)r;
    }
    unsigned pos = atomicAdd(&((uint32_t*)g_binScan4)[bin], 1u);
    g_sorted[pos] = make_uint4((unsigned)r, (unsigned)c, __float_as_uint(v), e);
    if (tid < NBINP) ((uint32_t*)g_bins4)[tid] = 0u;   // zero-on-exit for hist
}

// ---------------- fused mask + row-sorted edge-parallel SPMM --------------------
// (retry of the round-12 candidate: infra failed before execution)
// Warp = 32 consecutive sorted edges. Each lane loads ONE record (512B coalesced)
// and computes ONE threefry mask (no duplication). Two 16-lane slots each process
// 16 consecutive edges as 2 batches of 8 MLP gathers (UNCONDITIONAL: gathers
// depend only on shuffled cols, never on the threefry chain) with a carried
// (row, acc) register aggregation across batches; REDs only on row change.
template <int LAYER>
__global__ void spmm_kernel(const float4* __restrict__ u4,
                            const float4* __restrict__ i4,
                            const float4* __restrict__ t4,
                            uint32_t ka1, uint32_t ka2, uint32_t kt1, uint32_t kt2,
                            uint32_t ku1, uint32_t ku2) {
    unsigned bid = blockIdx.x;
    float4* outb; int mode; uint32_t k1, k2;
    if (bid < A_BLK)                { outb = g_tem;       mode = 0; k1 = ka1; k2 = ka2; }
    else if (bid < A_BLK + T_BLK)   { outb = g_tg[LAYER]; mode = 1; k1 = kt1; k2 = kt2; }
    else                            { outb = g_soc;       mode = 2; k1 = ku1; k2 = ku2; }
    unsigned lane  = threadIdx.x & 31u;
    unsigned warp  = threadIdx.x >> 5;
    unsigned chunk = lane & 15u;
    unsigned slot  = lane >> 4;
    unsigned wbase = bid * EPB + warp * 32u;

    // one record + one threefry per lane (= per edge; pads are all-zero -> mval=0)
    uint4 rec = __ldg(&g_sorted[wbase + lane]);
    uint32_t bits = tf_bits(k1, k2, rec.w);
    float u    = __uint_as_float((bits >> 9) | 0x3f800000u) - 1.0f;
    float mval = (__uint_as_float(rec.z) * floorf(u + 0.9f)) * (float)(1.0 / 0.9);

    int   cur = -1;
    float4 acc = make_float4(0.f, 0.f, 0.f, 0.f);
    bool touched = false;
#pragma unroll
    for (int b = 0; b < 2; ++b) {
        float v[8]; int rr[8], cc[8];
#pragma unroll
        for (int j = 0; j < 8; ++j) {
            int src = (int)(slot * 16u) + b * 8 + j;
            v[j]  = __shfl_sync(0xffffffffu, mval,       src);
            rr[j] = __shfl_sync(0xffffffffu, (int)rec.x, src);
            cc[j] = __shfl_sync(0xffffffffu, (int)rec.y, src);
        }
        // unconditional MLP gathers (addresses independent of threefry)
        float4 xv[8];
#pragma unroll
        for (int j = 0; j < 8; ++j) {
            int c = cc[j];
            const float4* x;
            if (LAYER == 0) {
                if (mode == 1)
                    x = (c < ITEM_N) ? (i4 + (unsigned)c * R4)
                                     : (t4 + (unsigned)(c - ITEM_N) * R4);
                else
                    x = (c < USER_N) ? (u4 + (unsigned)c * R4)
                                     : (i4 + (unsigned)(c - USER_N) * R4);
            } else {
                if (mode == 1)
                    x = (c < ITEM_N) ? (g_lat + (unsigned)(USER_N + c) * R4)
                                     : (g_taglat + (unsigned)c * R4);
                else
                    x = g_lat + (unsigned)c * R4;
            }
            xv[j] = __ldg(x + chunk);
        }
        // carried register aggregation over same-row runs
#pragma unroll
        for (int j = 0; j < 8; ++j) {
            if (rr[j] != cur) {
                if (touched) {
                    float4* dst = outb + (unsigned)cur * R4 + chunk;
                    asm volatile("red.global.add.v4.f32 [%0], {%1,%2,%3,%4};"
                                 :: "l"(dst), "f"(acc.x), "f"(acc.y), "f"(acc.z), "f"(acc.w)
                                 : "memory");
                }
                cur = rr[j]; acc = make_float4(0.f, 0.f, 0.f, 0.f); touched = false;
            }
            if (v[j] != 0.f) {
                acc.x += v[j] * xv[j].x; acc.y += v[j] * xv[j].y;
                acc.z += v[j] * xv[j].z; acc.w += v[j] * xv[j].w;
                touched = true;
            }
        }
    }
    if (touched) {
        float4* dst = outb + (unsigned)cur * R4 + chunk;
        asm volatile("red.global.add.v4.f32 [%0], {%1,%2,%3,%4};"
                     :: "l"(dst), "f"(acc.x), "f"(acc.y), "f"(acc.z), "f"(acc.w)
                     : "memory");
    }
}

// combine-mid: lat = leaky(tem)+leaky(soc|tg0); taglat(tag part) = leaky(tg0);
// zero tem + soc (same-thread-after-read). tg[0] is zeroed later by fin.
__global__ void mid_kernel() {
    const float4 z = make_float4(0.f, 0.f, 0.f, 0.f);
    unsigned base = blockIdx.x * (2u * TB) + threadIdx.x;
    unsigned ia = base, ib = base + TB;
    bool va = ia < NELEM, vb = ib < NELEM;
    unsigned a = va ? ia : 0u, b = vb ? ib : 0u;
    bool ua = a < UELEM, ub = b < UELEM;
    bool ga = (a >= IELEM) & (a < GELEM);
    bool gb = (b >= IELEM) & (b < GELEM);
    float4 ta  = g_tem[a];
    float4 tb4 = g_tem[b];
    float4 sa  = ua ? g_soc[a] : g_tg[0][a - UELEM];
    float4 sb  = ub ? g_soc[b] : g_tg[0][b - UELEM];
    float4 g0a = ga ? g_tg[0][a] : z;
    float4 g0b = gb ? g_tg[0][b] : z;
    float4 oa = add4(leaky4(ta),  leaky4(sa));
    float4 ob = add4(leaky4(tb4), leaky4(sb));
    if (va) {
        g_lat[a] = oa; g_tem[a] = z;
        if (ua) g_soc[a] = z;
        if (ga) g_taglat[a] = leaky4(g0a);
    }
    if (vb) {
        g_lat[b] = ob; g_tem[b] = z;
        if (ub) g_soc[b] = z;
        if (gb) g_taglat[b] = leaky4(g0b);
    }
}

// combine-final: out = (u|i) + g_lat + leaky(tem) + leaky(soc|tg1); re-zero state.
__global__ void fin_kernel(float4* __restrict__ out,
                           const float4* __restrict__ u4,
                           const float4* __restrict__ i4) {
    const float4 z = make_float4(0.f, 0.f, 0.f, 0.f);
    unsigned base = blockIdx.x * (2u * TB) + threadIdx.x;
    unsigned ia = base, ib = base + TB;
    bool va = ia < NELEM, vb = ib < NELEM;
    unsigned a = va ? ia : 0u, b = vb ? ib : 0u;
    bool ua = a < UELEM, ub = b < UELEM;
    float4 ta  = g_tem[a];
    float4 tb4 = g_tem[b];
    float4 sa  = ua ? g_soc[a] : g_tg[1][a - UELEM];
    float4 sb  = ub ? g_soc[b] : g_tg[1][b - UELEM];
    float4 la  = g_lat[a];
    float4 lb  = g_lat[b];
    float4 ea  = ua ? __ldg(u4 + a) : __ldg(i4 + a - UELEM);
    float4 eb  = ub ? __ldg(u4 + b) : __ldg(i4 + b - UELEM);
    float4 l2a = add4(leaky4(ta),  leaky4(sa));
    float4 l2b = add4(leaky4(tb4), leaky4(sb));
    if (va) {
        out[a] = add4(add4(ea, la), l2a);
        g_tem[a] = z;
        if (ua) g_soc[a] = z; else g_tg[1][a - UELEM] = z;
    }
    if (vb) {
        out[b] = add4(add4(eb, lb), l2b);
        g_tem[b] = z;
        if (ub) g_soc[b] = z; else g_tg[1][b - UELEM] = z;
    }
    // zero buffers nobody reads here: all of tg[0], tg[1] tag tail
    const unsigned NTHR = (unsigned)COMBB * TB;
    unsigned gt = blockIdx.x * TB + threadIdx.x;
    for (unsigned k = gt; k < GELEM + TELEM; k += NTHR) {
        if (k < GELEM) g_tg[0][k] = z;
        else           g_tg[1][IELEM + (k - GELEM)] = z;
    }
}

// ---------------- launch ----------------
extern "C" void kernel_launch(void* const* d_in, const int* in_sizes, int n_in,
                              void* d_out, int out_size) {
    const float4* uE = (const float4*)d_in[0];
    const float4* iE = (const float4*)d_in[1];
    const float4* tE = (const float4*)d_in[2];
    const int*   ar = (const int*)d_in[3];
    const int*   ac = (const int*)d_in[4];
    const float* av = (const float*)d_in[5];
    const int*   tr = (const int*)d_in[6];
    const int*   tc = (const int*)d_in[7];
    const float* tv = (const float*)d_in[8];
    const int*   sr = (const int*)d_in[9];
    const int*   sc = (const int*)d_in[10];
    const float* sv = (const float*)d_in[11];
    float4* out = (float4*)d_out;

    // jax.random.key(42) -> (0, 42); fold_in(key, j) = threefry2x32(key, (0, j))
    uint32_t fk[6][2];
    for (uint32_t j = 0; j < 6; ++j)
        h_threefry(0u, 42u, 0u, j, &fk[j][0], &fk[j][1]);

    // row-sort the edge lists (shared by both layers)
    hist_kernel<<<EB, TB>>>(ar, tr, sr);
    scanA_kernel<<<SCANB, 256>>>();
    scanB_kernel<<<1, 512>>>();
    scanC_kernel<<<SCANB, 256>>>();
    scatter_kernel<<<EB, TB>>>(ar, ac, av, tr, tc, tv, sr, sc, sv);

    // layer 0: fused mask+spmm from input embeddings
    spmm_kernel<0><<<SPMMB, TB>>>(uE, iE, tE,
                                  fk[0][0], fk[0][1], fk[1][0], fk[1][1],
                                  fk[2][0], fk[2][1]);
    mid_kernel<<<COMBB, TB>>>();
    // layer 1: fused mask+spmm from g_lat / g_taglat
    spmm_kernel<1><<<SPMMB, TB>>>(uE, iE, tE,
                                  fk[3][0], fk[3][1], fk[4][0], fk[4][1],
                                  fk[5][0], fk[5][1]);
    fin_kernel<<<COMBB, TB>>>(out, uE, iE);
}

// round 14
// speedup vs baseline: 1.5924x; 1.0728x over previous
#include <cuda_runtime.h>
#include <stdint.h>

// ---------------- problem constants ----------------
#define USER_N 100000
#define ITEM_N 50000
#define TAG_N  20000
#define NADJ   (USER_N + ITEM_N)   // 150000
#define MTAG   (ITEM_N + TAG_N)    // 70000
#define EADJ   2000000
#define ETAG   1000000
#define ESOC   1000000
#define ETOT   4000000
#define R4     16                    // D=64 floats = 16 float4
#define NELEM  (NADJ * R4)           // 2,400,000 float4
#define UELEM  (USER_N * R4)
#define IELEM  (ITEM_N * R4)
#define GELEM  (MTAG * R4)
#define TB     256

// sorted layout, regions padded to 512-edge multiples:
// adj [0, 2,000,384) | tag [2,000,384, 3,000,832) | soc [3,000,832, 4,001,280)
#define TAG_BASE  2000384
#define SOC_BASE  3000832
#define SORT_N    4001280
#define EPB    512                   // edges per spmm block (64 per warp)
#define A_BLK  (TAG_BASE / EPB)              // 3907
#define T_BLK  ((SOC_BASE - TAG_BASE) / EPB) // 1954
#define S_BLK  ((SORT_N - SOC_BASE) / EPB)   // 1954
#define SPMMB  (A_BLK + T_BLK + S_BLK)       // 7815
#define COMBB  ((NELEM + 2 * TB - 1) / (2 * TB))   // 4688

// bins: adj rows [0,150K) | tag rows [150K,220K) | soc rows [220K,320K)
#define NBINS  (NADJ + MTAG + USER_N)        // 320000
#define SOC_BIN0 (NADJ + MTAG)               // 220000
#define SCANB  313
#define NBINP  (SCANB * 1024)                // 320512 (padded)
#define EB     (ETOT / TB)                   // 15625

// call-start zeroing (fused into hist): tem | soc | tg[0] | tg[1]
#define ZELEM  (NELEM + UELEM + 2 * GELEM)   // 6,240,000 float4
#define ZPT    4
#define ZBLK   ((ZELEM + TB * ZPT - 1) / (TB * ZPT))   // 6094

// ---------------- device scratch ----------------
__device__ float4 g_lat[NELEM];
__device__ float4 g_taglat[GELEM];
__device__ float4 g_tem[NELEM];           // zeroed in hist phase each call
__device__ float4 g_tg[2][GELEM];         // zeroed in hist phase each call
__device__ float4 g_soc[UELEM];           // zeroed in hist phase each call
__device__ uint4  g_bins4[NBINP / 4];     // histogram (zeroed by scatter each call)
__device__ uint4  g_binScan4[NBINP / 4];  // scatter cursors (rewritten each call)
__device__ uint32_t g_blkSum[SCANB];
__device__ uint32_t g_blkOff[SCANB];
__device__ uint4  g_sorted[SORT_N];       // (row, col, val_bits, local_idx); pads stay 0

// ---------------- threefry-2x32-20 (JAX partitionable, bit-exact) ----------------
__device__ __forceinline__ uint32_t d_rotl(uint32_t v, int r) {
    return __funnelshift_l(v, v, r);
}
__device__ __forceinline__ uint32_t tf_bits(uint32_t K1, uint32_t K2, uint32_t ctr) {
    uint32_t ks2 = K1 ^ K2 ^ 0x1BD11BDAu;
    uint32_t x0 = K1;
    uint32_t x1 = ctr + K2;
#define TF_R4(a,b,c,d)                                        \
    x0 += x1; x1 = d_rotl(x1,a); x1 ^= x0;                    \
    x0 += x1; x1 = d_rotl(x1,b); x1 ^= x0;                    \
    x0 += x1; x1 = d_rotl(x1,c); x1 ^= x0;                    \
    x0 += x1; x1 = d_rotl(x1,d); x1 ^= x0;
    TF_R4(13,15,26,6)   x0 += K2;  x1 += ks2 + 1u;
    TF_R4(17,29,16,24)  x0 += ks2; x1 += K1  + 2u;
    TF_R4(13,15,26,6)   x0 += K1;  x1 += K2  + 3u;
    TF_R4(17,29,16,24)  x0 += K2;  x1 += ks2 + 4u;
    TF_R4(13,15,26,6)   x0 += ks2; x1 += K1  + 5u;
#undef TF_R4
    return x0 ^ x1;
}

static inline uint32_t h_rotl(uint32_t v, int r) { return (v << r) | (v >> (32 - r)); }
static void h_threefry(uint32_t K1, uint32_t K2, uint32_t x0, uint32_t x1,
                       uint32_t* o0, uint32_t* o1) {
    uint32_t ks[3] = {K1, K2, K1 ^ K2 ^ 0x1BD11BDAu};
    static const int rots[2][4] = {{13,15,26,6},{17,29,16,24}};
    x0 += ks[0]; x1 += ks[1];
    for (int g = 0; g < 5; ++g) {
        const int* rr = rots[g & 1];
        for (int j = 0; j < 4; ++j) { x0 += x1; x1 = h_rotl(x1, rr[j]); x1 ^= x0; }
        x0 += ks[(g + 1) % 3];
        x1 += ks[(g + 2) % 3] + (uint32_t)(g + 1);
    }
    *o0 = x0; *o1 = x1;
}

// ---------------- helpers ----------------
__device__ __forceinline__ float4 leaky4(float4 h) {
    h.x = h.x >= 0.f ? h.x : 0.5f * h.x;
    h.y = h.y >= 0.f ? h.y : 0.5f * h.y;
    h.z = h.z >= 0.f ? h.z : 0.5f * h.z;
    h.w = h.w >= 0.f ? h.w : 0.5f * h.w;
    return h;
}
__device__ __forceinline__ float4 add4(float4 a, float4 b) {
    return make_float4(a.x + b.x, a.y + b.y, a.z + b.z, a.w + b.w);
}

// ---------------- sort pipeline ----------------
// Blocks [0, EB): edge histogram (atomic-bound, DRAM idle).
// Blocks [EB, EB+ZBLK): zero tem|soc|tg[0]|tg[1] (rides the idle DRAM).
__global__ void hist_kernel(const int* __restrict__ ar,
                            const int* __restrict__ tr,
                            const int* __restrict__ sr) {
    if (blockIdx.x < EB) {
        unsigned tid = blockIdx.x * TB + threadIdx.x;      // < ETOT
        unsigned bin;
        if (tid < EADJ)               bin = (unsigned)__ldg(ar + tid);
        else if (tid < EADJ + ETAG)   bin = NADJ + (unsigned)__ldg(tr + (tid - EADJ));
        else                          bin = SOC_BIN0 + (unsigned)__ldg(sr + (tid - EADJ - ETAG));
        atomicAdd(&((uint32_t*)g_bins4)[bin], 1u);
        return;
    }
    const float4 z = make_float4(0.f, 0.f, 0.f, 0.f);
    unsigned zb = blockIdx.x - EB;
#pragma unroll
    for (int i = 0; i < ZPT; ++i) {
        unsigned idx = zb * (TB * ZPT) + (unsigned)i * TB + threadIdx.x;
        if (idx < NELEM)                         g_tem[idx] = z;
        else if (idx < NELEM + UELEM)            g_soc[idx - NELEM] = z;
        else if (idx < NELEM + UELEM + GELEM)    g_tg[0][idx - NELEM - UELEM] = z;
        else if (idx < ZELEM)                    g_tg[1][idx - NELEM - UELEM - GELEM] = z;
    }
}

__global__ void scanA_kernel() {
    unsigned t = threadIdx.x, b = blockIdx.x;
    uint4 v = g_bins4[b * 256 + t];
    uint32_t sum = v.x + v.y + v.z + v.w;
    uint32_t incl = sum;
#pragma unroll
    for (int d = 1; d < 32; d <<= 1) {
        uint32_t n = __shfl_up_sync(0xffffffffu, incl, d);
        if ((t & 31u) >= (unsigned)d) incl += n;
    }
    __shared__ uint32_t ws[8], wo[8];
    if ((t & 31u) == 31u) ws[t >> 5] = incl;
    __syncthreads();
    if (t == 0) {
        uint32_t run = 0;
#pragma unroll
        for (int i = 0; i < 8; ++i) { wo[i] = run; run += ws[i]; }
        g_blkSum[b] = run;
    }
    __syncthreads();
    uint32_t excl = incl - sum + wo[t >> 5];
    uint4 o;
    o.x = excl; o.y = excl + v.x; o.z = o.y + v.y; o.w = o.z + v.z;
    g_binScan4[b * 256 + t] = o;
}

__global__ void scanB_kernel() {
    unsigned t = threadIdx.x;                 // 512 threads
    uint32_t sum = (t < SCANB) ? g_blkSum[t] : 0u;
    uint32_t incl = sum;
#pragma unroll
    for (int d = 1; d < 32; d <<= 1) {
        uint32_t n = __shfl_up_sync(0xffffffffu, incl, d);
        if ((t & 31u) >= (unsigned)d) incl += n;
    }
    __shared__ uint32_t ws[16], wo[16];
    if ((t & 31u) == 31u) ws[t >> 5] = incl;
    __syncthreads();
    if (t == 0) {
        uint32_t run = 0;
#pragma unroll
        for (int i = 0; i < 16; ++i) { wo[i] = run; run += ws[i]; }
    }
    __syncthreads();
    if (t < SCANB) g_blkOff[t] = incl - sum + wo[t >> 5];
}

// finalize bin starts; region pad shifts: tag bins +384, soc bins +832
__global__ void scanC_kernel() {
    unsigned t = threadIdx.x, b = blockIdx.x;
    unsigned idx4 = b * 256 + t;
    uint32_t add = g_blkOff[b]
                 + ((idx4 >= NADJ / 4)     ? 384u : 0u)
                 + ((idx4 >= SOC_BIN0 / 4) ? 448u : 0u);
    uint4 v = g_binScan4[idx4];
    v.x += add; v.y += add; v.z += add; v.w += add;
    g_binScan4[idx4] = v;
}

// scatter edges into row-sorted order; re-zero histogram bins
__global__ void scatter_kernel(const int* __restrict__ ar, const int* __restrict__ ac,
                               const float* __restrict__ av,
                               const int* __restrict__ tr, const int* __restrict__ tc,
                               const float* __restrict__ tv,
                               const int* __restrict__ sr, const int* __restrict__ sc,
                               const float* __restrict__ sv) {
    unsigned tid = blockIdx.x * TB + threadIdx.x;      // < ETOT
    unsigned e, bin; int r, c; float v;
    if (tid < EADJ) {
        e = tid;               r = __ldg(ar + e); c = __ldg(ac + e); v = __ldg(av + e); bin = (unsigned)r;
    } else if (tid < EADJ + ETAG) {
        e = tid - EADJ;        r = __ldg(tr + e); c = __ldg(tc + e); v = __ldg(tv + e); bin = NADJ + (unsigned)r;
    } else {
        e = tid - EADJ - ETAG; r = __ldg(sr + e); c = __ldg(sc + e); v = __ldg(sv + e); bin = SOC_BIN0 + (unsigned)r;
    }
    unsigned pos = atomicAdd(&((uint32_t*)g_binScan4)[bin], 1u);
    g_sorted[pos] = make_uint4((unsigned)r, (unsigned)c, __float_as_uint(v), e);
    if (tid < NBINP) ((uint32_t*)g_bins4)[tid] = 0u;   // zero-on-exit for hist
}

// ---------------- fused mask + row-sorted edge-parallel SPMM --------------------
// Warp = 64 consecutive sorted edges. Lanes 0..15 (slot 0) own edges [0,32):
// recA = edge (lane&15), recB = edge 16+(lane&15); lanes 16..31 (slot 1) own
// edges [32,64) likewise. One threefry per record (= per edge, no duplication).
// Each slot processes its 32 edges as 4 batches of 8 MLP gathers (unconditional;
// addresses depend only on shuffled cols) with carried (row, acc) register
// aggregation across the whole 32-edge window; REDs only on row change.
template <int LAYER>
__global__ void spmm_kernel(const float4* __restrict__ u4,
                            const float4* __restrict__ i4,
                            const float4* __restrict__ t4,
                            uint32_t ka1, uint32_t ka2, uint32_t kt1, uint32_t kt2,
                            uint32_t ku1, uint32_t ku2) {
    unsigned bid = blockIdx.x;
    float4* outb; int mode; uint32_t k1, k2;
    if (bid < A_BLK)                { outb = g_tem;       mode = 0; k1 = ka1; k2 = ka2; }
    else if (bid < A_BLK + T_BLK)   { outb = g_tg[LAYER]; mode = 1; k1 = kt1; k2 = kt2; }
    else                            { outb = g_soc;       mode = 2; k1 = ku1; k2 = ku2; }
    unsigned lane  = threadIdx.x & 31u;
    unsigned warp  = threadIdx.x >> 5;
    unsigned chunk = lane & 15u;
    unsigned slot  = lane >> 4;
    unsigned wbase = bid * EPB + warp * 64u;

    // slot-local records: slot s lanes hold edges [s*32, s*32+32)
    unsigned eA = wbase + slot * 32u + chunk;        // edges s*32 + [0,16)
    unsigned eB = eA + 16u;                          // edges s*32 + [16,32)
    uint4 recA = __ldg(&g_sorted[eA]);
    uint4 recB = __ldg(&g_sorted[eB]);
    uint32_t bitsA = tf_bits(k1, k2, recA.w);
    uint32_t bitsB = tf_bits(k1, k2, recB.w);
    float uA = __uint_as_float((bitsA >> 9) | 0x3f800000u) - 1.0f;
    float uB = __uint_as_float((bitsB >> 9) | 0x3f800000u) - 1.0f;
    float mvalA = (__uint_as_float(recA.z) * floorf(uA + 0.9f)) * (float)(1.0 / 0.9);
    float mvalB = (__uint_as_float(recB.z) * floorf(uB + 0.9f)) * (float)(1.0 / 0.9);

    int   cur = -1;
    float4 acc = make_float4(0.f, 0.f, 0.f, 0.f);
    bool touched = false;
#pragma unroll
    for (int b = 0; b < 4; ++b) {                 // 4 batches of 8 = 32 edges/slot
        float v[8]; int rr[8], cc[8];
#pragma unroll
        for (int j = 0; j < 8; ++j) {
            int src = (int)(slot * 16u) + (b & 1) * 8 + j;   // lane holding this edge
            if (b < 2) {                                       // edges [0,16): recA
                v[j]  = __shfl_sync(0xffffffffu, mvalA,       src);
                rr[j] = __shfl_sync(0xffffffffu, (int)recA.x, src);
                cc[j] = __shfl_sync(0xffffffffu, (int)recA.y, src);
            } else {                                           // edges [16,32): recB
                v[j]  = __shfl_sync(0xffffffffu, mvalB,       src);
                rr[j] = __shfl_sync(0xffffffffu, (int)recB.x, src);
                cc[j] = __shfl_sync(0xffffffffu, (int)recB.y, src);
            }
        }
        // unconditional MLP gathers (addresses independent of threefry)
        float4 xv[8];
#pragma unroll
        for (int j = 0; j < 8; ++j) {
            int c = cc[j];
            const float4* x;
            if (LAYER == 0) {
                if (mode == 1)
                    x = (c < ITEM_N) ? (i4 + (unsigned)c * R4)
                                     : (t4 + (unsigned)(c - ITEM_N) * R4);
                else
                    x = (c < USER_N) ? (u4 + (unsigned)c * R4)
                                     : (i4 + (unsigned)(c - USER_N) * R4);
            } else {
                if (mode == 1)
                    x = (c < ITEM_N) ? (g_lat + (unsigned)(USER_N + c) * R4)
                                     : (g_taglat + (unsigned)c * R4);
                else
                    x = g_lat + (unsigned)c * R4;
            }
            xv[j] = __ldg(x + chunk);
        }
        // carried register aggregation over same-row runs (32-edge window)
#pragma unroll
        for (int j = 0; j < 8; ++j) {
            if (rr[j] != cur) {
                if (touched) {
                    float4* dst = outb + (unsigned)cur * R4 + chunk;
                    asm volatile("red.global.add.v4.f32 [%0], {%1,%2,%3,%4};"
                                 :: "l"(dst), "f"(acc.x), "f"(acc.y), "f"(acc.z), "f"(acc.w)
                                 : "memory");
                }
                cur = rr[j]; acc = make_float4(0.f, 0.f, 0.f, 0.f); touched = false;
            }
            if (v[j] != 0.f) {
                acc.x += v[j] * xv[j].x; acc.y += v[j] * xv[j].y;
                acc.z += v[j] * xv[j].z; acc.w += v[j] * xv[j].w;
                touched = true;
            }
        }
    }
    if (touched) {
        float4* dst = outb + (unsigned)cur * R4 + chunk;
        asm volatile("red.global.add.v4.f32 [%0], {%1,%2,%3,%4};"
                     :: "l"(dst), "f"(acc.x), "f"(acc.y), "f"(acc.z), "f"(acc.w)
                     : "memory");
    }
}

// combine-mid: lat = leaky(tem)+leaky(soc|tg0); taglat(tag part) = leaky(tg0);
// zero tem + soc for spmm1 (same-thread-after-read; race-free).
__global__ void mid_kernel() {
    const float4 z = make_float4(0.f, 0.f, 0.f, 0.f);
    unsigned base = blockIdx.x * (2u * TB) + threadIdx.x;
    unsigned ia = base, ib = base + TB;
    bool va = ia < NELEM, vb = ib < NELEM;
    unsigned a = va ? ia : 0u, b = vb ? ib : 0u;
    bool ua = a < UELEM, ub = b < UELEM;
    bool ga = (a >= IELEM) & (a < GELEM);
    bool gb = (b >= IELEM) & (b < GELEM);
    float4 ta  = g_tem[a];
    float4 tb4 = g_tem[b];
    float4 sa  = ua ? g_soc[a] : g_tg[0][a - UELEM];
    float4 sb  = ub ? g_soc[b] : g_tg[0][b - UELEM];
    float4 g0a = ga ? g_tg[0][a] : z;
    float4 g0b = gb ? g_tg[0][b] : z;
    float4 oa = add4(leaky4(ta),  leaky4(sa));
    float4 ob = add4(leaky4(tb4), leaky4(sb));
    if (va) {
        g_lat[a] = oa; g_tem[a] = z;
        if (ua) g_soc[a] = z;
        if (ga) g_taglat[a] = leaky4(g0a);
    }
    if (vb) {
        g_lat[b] = ob; g_tem[b] = z;
        if (ub) g_soc[b] = z;
        if (gb) g_taglat[b] = leaky4(g0b);
    }
}

// combine-final: out = (u|i) + g_lat + leaky(tem) + leaky(soc|tg1).
// NO zero-stores, NO tail loop: all call-start zeroing lives in hist phase.
__global__ void fin_kernel(float4* __restrict__ out,
                           const float4* __restrict__ u4,
                           const float4* __restrict__ i4) {
    unsigned base = blockIdx.x * (2u * TB) + threadIdx.x;
    unsigned ia = base, ib = base + TB;
    bool va = ia < NELEM, vb = ib < NELEM;
    unsigned a = va ? ia : 0u, b = vb ? ib : 0u;
    bool ua = a < UELEM, ub = b < UELEM;
    float4 ta  = g_tem[a];
    float4 tb4 = g_tem[b];
    float4 sa  = ua ? g_soc[a] : g_tg[1][a - UELEM];
    float4 sb  = ub ? g_soc[b] : g_tg[1][b - UELEM];
    float4 la  = g_lat[a];
    float4 lb  = g_lat[b];
    float4 ea  = ua ? __ldg(u4 + a) : __ldg(i4 + a - UELEM);
    float4 eb  = ub ? __ldg(u4 + b) : __ldg(i4 + b - UELEM);
    float4 l2a = add4(leaky4(ta),  leaky4(sa));
    float4 l2b = add4(leaky4(tb4), leaky4(sb));
    if (va) out[a] = add4(add4(ea, la), l2a);
    if (vb) out[b] = add4(add4(eb, lb), l2b);
}

// ---------------- launch ----------------
extern "C" void kernel_launch(void* const* d_in, const int* in_sizes, int n_in,
                              void* d_out, int out_size) {
    const float4* uE = (const float4*)d_in[0];
    const float4* iE = (const float4*)d_in[1];
    const float4* tE = (const float4*)d_in[2];
    const int*   ar = (const int*)d_in[3];
    const int*   ac = (const int*)d_in[4];
    const float* av = (const float*)d_in[5];
    const int*   tr = (const int*)d_in[6];
    const int*   tc = (const int*)d_in[7];
    const float* tv = (const float*)d_in[8];
    const int*   sr = (const int*)d_in[9];
    const int*   sc = (const int*)d_in[10];
    const float* sv = (const float*)d_in[11];
    float4* out = (float4*)d_out;

    // jax.random.key(42) -> (0, 42); fold_in(key, j) = threefry2x32(key, (0, j))
    uint32_t fk[6][2];
    for (uint32_t j = 0; j < 6; ++j)
        h_threefry(0u, 42u, 0u, j, &fk[j][0], &fk[j][1]);

    // row-sort the edge lists (shared by both layers) + call-start zeroing
    hist_kernel<<<EB + ZBLK, TB>>>(ar, tr, sr);
    scanA_kernel<<<SCANB, 256>>>();
    scanB_kernel<<<1, 512>>>();
    scanC_kernel<<<SCANB, 256>>>();
    scatter_kernel<<<EB, TB>>>(ar, ac, av, tr, tc, tv, sr, sc, sv);

    // layer 0: fused mask+spmm from input embeddings
    spmm_kernel<0><<<SPMMB, TB>>>(uE, iE, tE,
                                  fk[0][0], fk[0][1], fk[1][0], fk[1][1],
                                  fk[2][0], fk[2][1]);
    mid_kernel<<<COMBB, TB>>>();
    // layer 1: fused mask+spmm from g_lat / g_taglat
    spmm_kernel<1><<<SPMMB, TB>>>(uE, iE, tE,
                                  fk[3][0], fk[3][1], fk[4][0], fk[4][1],
                                  fk[5][0], fk[5][1]);
    fin_kernel<<<COMBB, TB>>>(out, uE, iE);
}